// round 2
// baseline (speedup 1.0000x reference)
#include <cuda_runtime.h>

#define NCELLS   19683
#define KNB      26
#define ROWS     64
#define NTHREADS 256
#define XP       132   // Xs row pitch (floats)
#define WPP      132   // Ws row pitch (floats)
#define GP       36    // Gs row pitch (floats)

// ---------------- scratch (device globals: allocation-free) ----------------
__device__ float g_mean_l[NCELLS * 64];
__device__ float g_mean_f[NCELLS * 64];
__device__ float g_mean_d[NCELLS * 64];
__device__ float g_act[NCELLS * 64];
__device__ int   g_flags[NCELLS];

typedef unsigned long long ull;

__device__ __forceinline__ ull pack2(float x, float y) {
    ull r; asm("mov.b64 %0, {%1,%2};" : "=l"(r) : "f"(x), "f"(y)); return r;
}
__device__ __forceinline__ float2 unpack2(ull v) {
    float2 r; asm("mov.b64 {%0,%1}, %2;" : "=f"(r.x), "=f"(r.y) : "l"(v)); return r;
}
__device__ __forceinline__ void ffma2(ull& acc, ull a, ull b) {
    asm("fma.rn.f32x2 %0, %1, %2, %0;" : "+l"(acc) : "l"(a), "l"(b));
}

// ---------------- kernel A: masked neighbor aggregation ----------------
// one warp per cell; lane handles cols {2l, 2l+1}
__global__ void agg_kernel(const float* __restrict__ nb, const int* __restrict__ cat) {
    int gw = (blockIdx.x * blockDim.x + threadIdx.x) >> 5;
    if (gw >= NCELLS) return;
    int lane = threadIdx.x & 31;
    const float* base = nb + (size_t)gw * (KNB * 64);
    int myc = (lane < KNB) ? cat[gw * KNB + lane] : 0;

    float2 s0 = {0.f, 0.f}, s1 = {0.f, 0.f}, s2 = {0.f, 0.f}, sa = {0.f, 0.f};
    int c0 = 0, c1 = 0, c2 = 0;
#pragma unroll
    for (int k = 0; k < KNB; k++) {
        int c = __shfl_sync(0xffffffffu, myc, k);
        float2 v = *(const float2*)(base + k * 64 + lane * 2);
        sa.x += v.x; sa.y += v.y;
        if (c == 0)      { s0.x += v.x; s0.y += v.y; c0++; }
        else if (c == 1) { s1.x += v.x; s1.y += v.y; c1++; }
        else             { s2.x += v.x; s2.y += v.y; c2++; }
    }
    float d0 = fmaxf((float)c0, 1.0f);
    float d1 = fmaxf((float)c1, 1.0f);
    float d2 = fmaxf((float)c2, 1.0f);
    int off = gw * 64 + lane * 2;
    *(float2*)(g_mean_l + off) = make_float2(s0.x / d0, s0.y / d0);
    *(float2*)(g_mean_f + off) = make_float2(s1.x / d1, s1.y / d1);
    *(float2*)(g_mean_d + off) = make_float2(s2.x / d2, s2.y / d2);
    *(float2*)(g_act    + off) = make_float2(sa.x / 26.0f, sa.y / 26.0f);
    if (lane == 0)
        g_flags[gw] = (c0 > 0 ? 1 : 0) | (c1 > 0 ? 2 : 0) | (c2 > 0 ? 4 : 0);
}

// ---------------- kernel B helpers ----------------
template <int NC>
__device__ __forceinline__ void loadW(const float* __restrict__ Wg, float* Ws, int tid) {
    constexpr int PR = NC / 4;  // float4 per row
#pragma unroll
    for (int i = tid; i < 128 * PR; i += NTHREADS) {
        int r = i / PR, c = i % PR;
        *(float4*)&Ws[r * WPP + c * 4] = ((const float4*)Wg)[i];
    }
}

// fill Xs = [L | R], both [row][64] row-major in global, rows base..base+63
__device__ __forceinline__ void fillX(float* Xs, const float* __restrict__ L,
                                      const float* __restrict__ R,
                                      int tid, int base, int nrows) {
#pragma unroll
    for (int i = tid; i < 64 * 32; i += NTHREADS) {  // 2048 float4
        int r = i >> 5;
        int c4 = i & 31;
        int gr = base + r;
        float4 v = make_float4(0.f, 0.f, 0.f, 0.f);
        if (r < nrows) {
            if (c4 < 16) v = *(const float4*)(L + (size_t)gr * 64 + (c4 << 2));
            else         v = *(const float4*)(R + (size_t)gr * 64 + ((c4 - 16) << 2));
        }
        *(float4*)&Xs[r * XP + (c4 << 2)] = v;
    }
}

// fill only right half of Xs from R
__device__ __forceinline__ void fillXright(float* Xs, const float* __restrict__ R,
                                           int tid, int base, int nrows) {
#pragma unroll
    for (int i = tid; i < 64 * 16; i += NTHREADS) {
        int r = i >> 4;
        int c4 = i & 15;
        int gr = base + r;
        float4 v = make_float4(0.f, 0.f, 0.f, 0.f);
        if (r < nrows) v = *(const float4*)(R + (size_t)gr * 64 + (c4 << 2));
        *(float4*)&Xs[r * XP + 64 + (c4 << 2)] = v;
    }
}

// 64xTCgrid GEMM over K=128; fragment = 4 rows x TC cols per thread, packed f32x2 FMAs
template <int TC>
__device__ __forceinline__ void gemm128(const float* __restrict__ Xs,
                                        const float* __restrict__ Ws,
                                        int r0, int tx, ull (&acc)[4][TC / 2]) {
#pragma unroll
    for (int i = 0; i < 4; i++)
#pragma unroll
        for (int j = 0; j < TC / 2; j++) acc[i][j] = 0ULL;

#pragma unroll 2
    for (int k = 0; k < 128; k += 4) {
        float4 a[4];
#pragma unroll
        for (int i = 0; i < 4; i++) a[i] = *(const float4*)&Xs[(r0 + i) * XP + k];
#pragma unroll
        for (int kk = 0; kk < 4; kk++) {
            const float* bp = &Ws[(k + kk) * WPP + tx * TC];
            ull b[TC / 2];
            if constexpr (TC == 8) {
                ulonglong2 q0 = *(const ulonglong2*)bp;
                ulonglong2 q1 = *(const ulonglong2*)(bp + 4);
                b[0] = q0.x; b[1] = q0.y; b[2] = q1.x; b[3] = q1.y;
            } else if constexpr (TC == 4) {
                ulonglong2 q0 = *(const ulonglong2*)bp;
                b[0] = q0.x; b[1] = q0.y;
            } else {
                b[0] = *(const ull*)bp;
            }
#pragma unroll
            for (int i = 0; i < 4; i++) {
                float av = ((const float*)&a[i])[kk];
                ull ap = pack2(av, av);
#pragma unroll
                for (int j = 0; j < TC / 2; j++) ffma2(acc[i][j], ap, b[j]);
            }
        }
    }
}

// ---------------- kernel B: fused MoE MLP stack ----------------
__global__ void __launch_bounds__(NTHREADS, 2)
moe_kernel(const float* __restrict__ cur,
           const float* __restrict__ Wl,  const float* __restrict__ bl,
           const float* __restrict__ Wf1, const float* __restrict__ bf1,
           const float* __restrict__ Wf2, const float* __restrict__ bf2,
           const float* __restrict__ Wc1, const float* __restrict__ bc1,
           const float* __restrict__ Wc2, const float* __restrict__ bc2,
           const float* __restrict__ Wg1, const float* __restrict__ bg1,
           const float* __restrict__ Wg2, const float* __restrict__ bg2,
           float* __restrict__ out, int out_size) {
    extern __shared__ float sm[];
    float* Xs    = sm;                       // [64][XP]
    float* Ws    = Xs + ROWS * XP;           // [128][WPP]
    float* Gs    = Ws + 128 * WPP;           // [64][GP]
    float* sw    = Gs + ROWS * GP;           // [64][4]
    int*   sflag = (int*)(sw + ROWS * 4);    // [64]

    int tid  = threadIdx.x;
    int base = blockIdx.x * ROWS;
    int nrows = min(ROWS, NCELLS - base);

    int lane = tid & 31, warp = tid >> 5;
    int tx = (lane & 7) | ((warp & 1) << 3);   // 0..15
    int ty = (lane >> 3) | ((warp >> 1) << 2); // 0..15
    int r0 = ty * 4;

    if (tid < ROWS)
        sflag[tid] = (base + tid < NCELLS) ? g_flags[base + tid] : 0;

    // ================= gating =================
    fillX(Xs, cur, g_act, tid, base, nrows);
    loadW<32>(Wg1, Ws, tid);
    __syncthreads();
    {
        ull ag[4][1];
        gemm128<2>(Xs, Ws, r0, tx, ag);
        float2 bg = *(const float2*)&bg1[tx * 2];
#pragma unroll
        for (int i = 0; i < 4; i++) {
            float2 v = unpack2(ag[i][0]);
            float2 o = make_float2(tanhf(v.x + bg.x), tanhf(v.y + bg.y));
            *(float2*)&Gs[(r0 + i) * GP + tx * 2] = o;
        }
    }
    __syncthreads();
    if (tid < ROWS) {
        int row = tid;
        float l0 = bg2[0], l1 = bg2[1], l2 = bg2[2];
#pragma unroll
        for (int k = 0; k < 32; k++) {
            float gv = Gs[row * GP + k];
            l0 += gv * Wg2[k * 3 + 0];
            l1 += gv * Wg2[k * 3 + 1];
            l2 += gv * Wg2[k * 3 + 2];
        }
        float m = fmaxf(l0, fmaxf(l1, l2));
        float e0 = expf(l0 - m), e1 = expf(l1 - m), e2 = expf(l2 - m);
        float inv = 1.0f / (e0 + e1 + e2);
        float w0 = e0 * inv, w1 = e1 * inv, w2 = e2 * inv;
        sw[row * 4 + 0] = w0; sw[row * 4 + 1] = w1; sw[row * 4 + 2] = w2;
        int gr = base + row;
        if (gr < NCELLS && out_size >= NCELLS * 67) {
            out[(size_t)NCELLS * 64 + (size_t)gr * 3 + 0] = w0;
            out[(size_t)NCELLS * 64 + (size_t)gr * 3 + 1] = w1;
            out[(size_t)NCELLS * 64 + (size_t)gr * 3 + 2] = w2;
        }
    }
    __syncthreads();

    float2 comb[4][2];

    // ================= local expert =================
    fillX(Xs, cur, g_mean_l, tid, base, nrows);
    loadW<64>(Wl, Ws, tid);
    __syncthreads();
    {
        ull al[4][2];
        gemm128<4>(Xs, Ws, r0, tx, al);
        float2 b0 = *(const float2*)&bl[tx * 4];
        float2 b1 = *(const float2*)&bl[tx * 4 + 2];
#pragma unroll
        for (int i = 0; i < 4; i++) {
            int row = r0 + i;
            float w0 = sw[row * 4 + 0];
            bool on = (sflag[row] & 1);
            float2 v0 = unpack2(al[i][0]);
            float2 v1 = unpack2(al[i][1]);
            comb[i][0].x = on ? w0 * tanhf(v0.x + b0.x) : 0.f;
            comb[i][0].y = on ? w0 * tanhf(v0.y + b0.y) : 0.f;
            comb[i][1].x = on ? w0 * tanhf(v1.x + b1.x) : 0.f;
            comb[i][1].y = on ? w0 * tanhf(v1.y + b1.y) : 0.f;
        }
    }
    __syncthreads();

    // ================= functional expert =================
    fillX(Xs, cur, g_mean_f, tid, base, nrows);
    loadW<128>(Wf1, Ws, tid);
    __syncthreads();
    {
        ull ah[4][4];
        gemm128<8>(Xs, Ws, r0, tx, ah);
        __syncthreads();  // all threads done reading Xs/Ws
        float4 b0 = *(const float4*)&bf1[tx * 8];
        float4 b1 = *(const float4*)&bf1[tx * 8 + 4];
#pragma unroll
        for (int i = 0; i < 4; i++) {
            float2 v0 = unpack2(ah[i][0]), v1 = unpack2(ah[i][1]);
            float2 v2 = unpack2(ah[i][2]), v3 = unpack2(ah[i][3]);
            float4 o0 = make_float4(tanhf(v0.x + b0.x), tanhf(v0.y + b0.y),
                                    tanhf(v1.x + b0.z), tanhf(v1.y + b0.w));
            float4 o1 = make_float4(tanhf(v2.x + b1.x), tanhf(v2.y + b1.y),
                                    tanhf(v3.x + b1.z), tanhf(v3.y + b1.w));
            *(float4*)&Xs[(r0 + i) * XP + tx * 8]     = o0;
            *(float4*)&Xs[(r0 + i) * XP + tx * 8 + 4] = o1;
        }
        loadW<64>(Wf2, Ws, tid);
        __syncthreads();
        ull af[4][2];
        gemm128<4>(Xs, Ws, r0, tx, af);
        float2 c0 = *(const float2*)&bf2[tx * 4];
        float2 c1 = *(const float2*)&bf2[tx * 4 + 2];
#pragma unroll
        for (int i = 0; i < 4; i++) {
            int row = r0 + i;
            float w1 = sw[row * 4 + 1];
            bool on = (sflag[row] & 2);
            float2 v0 = unpack2(af[i][0]);
            float2 v1 = unpack2(af[i][1]);
            comb[i][0].x += on ? w1 * tanhf(v0.x + c0.x) : 0.f;
            comb[i][0].y += on ? w1 * tanhf(v0.y + c0.y) : 0.f;
            comb[i][1].x += on ? w1 * tanhf(v1.x + c1.x) : 0.f;
            comb[i][1].y += on ? w1 * tanhf(v1.y + c1.y) : 0.f;
        }
    }
    __syncthreads();

    // ================= distant expert (CNF, 3 Euler steps) =================
    float2 x[4][2];
#pragma unroll
    for (int i = 0; i < 4; i++) {
        int gr = base + r0 + i;
        float4 cv = make_float4(0.f, 0.f, 0.f, 0.f);
        if (gr < NCELLS) cv = *(const float4*)(cur + (size_t)gr * 64 + tx * 4);
        x[i][0] = make_float2(cv.x, cv.y);
        x[i][1] = make_float2(cv.z, cv.w);
    }
    const float DT = 1.0f / 3.0f;
    for (int step = 0; step < 3; step++) {
        // Xs = [x | mean_d]
#pragma unroll
        for (int i = 0; i < 4; i++) {
            float4 xv = make_float4(x[i][0].x, x[i][0].y, x[i][1].x, x[i][1].y);
            *(float4*)&Xs[(r0 + i) * XP + tx * 4] = xv;
        }
        fillXright(Xs, g_mean_d, tid, base, nrows);
        loadW<128>(Wc1, Ws, tid);
        __syncthreads();
        ull av[4][4];
        gemm128<8>(Xs, Ws, r0, tx, av);
        __syncthreads();
        {
            float4 b0 = *(const float4*)&bc1[tx * 8];
            float4 b1 = *(const float4*)&bc1[tx * 8 + 4];
#pragma unroll
            for (int i = 0; i < 4; i++) {
                float2 v0 = unpack2(av[i][0]), v1 = unpack2(av[i][1]);
                float2 v2 = unpack2(av[i][2]), v3 = unpack2(av[i][3]);
                float4 o0 = make_float4(tanhf(v0.x + b0.x), tanhf(v0.y + b0.y),
                                        tanhf(v1.x + b0.z), tanhf(v1.y + b0.w));
                float4 o1 = make_float4(tanhf(v2.x + b1.x), tanhf(v2.y + b1.y),
                                        tanhf(v3.x + b1.z), tanhf(v3.y + b1.w));
                *(float4*)&Xs[(r0 + i) * XP + tx * 8]     = o0;
                *(float4*)&Xs[(r0 + i) * XP + tx * 8 + 4] = o1;
            }
        }
        loadW<64>(Wc2, Ws, tid);
        __syncthreads();
        ull ad[4][2];
        gemm128<4>(Xs, Ws, r0, tx, ad);
        {
            float2 c0 = *(const float2*)&bc2[tx * 4];
            float2 c1 = *(const float2*)&bc2[tx * 4 + 2];
#pragma unroll
            for (int i = 0; i < 4; i++) {
                float2 v0 = unpack2(ad[i][0]);
                float2 v1 = unpack2(ad[i][1]);
                x[i][0].x += DT * tanhf(v0.x + c0.x);
                x[i][0].y += DT * tanhf(v0.y + c0.y);
                x[i][1].x += DT * tanhf(v1.x + c1.x);
                x[i][1].y += DT * tanhf(v1.y + c1.y);
            }
        }
        __syncthreads();
    }
#pragma unroll
    for (int i = 0; i < 4; i++) {
        int row = r0 + i;
        float w2 = sw[row * 4 + 2];
        bool on = (sflag[row] & 4);
        comb[i][0].x += on ? w2 * x[i][0].x : 0.f;
        comb[i][0].y += on ? w2 * x[i][0].y : 0.f;
        comb[i][1].x += on ? w2 * x[i][1].x : 0.f;
        comb[i][1].y += on ? w2 * x[i][1].y : 0.f;
    }

    // ================= store combined =================
#pragma unroll
    for (int i = 0; i < 4; i++) {
        int gr = base + r0 + i;
        if (gr < NCELLS) {
            float4 o = make_float4(comb[i][0].x, comb[i][0].y,
                                   comb[i][1].x, comb[i][1].y);
            *(float4*)&out[(size_t)gr * 64 + tx * 4] = o;
        }
    }
}

// ---------------- launch ----------------
extern "C" void kernel_launch(void* const* d_in, const int* in_sizes, int n_in,
                              void* d_out, int out_size) {
    const float* cur = (const float*)d_in[0];
    const float* nb  = (const float*)d_in[1];
    const int*   cat = (const int*)d_in[2];
    const float* Wl  = (const float*)d_in[3];
    const float* bl  = (const float*)d_in[4];
    const float* Wf1 = (const float*)d_in[5];
    const float* bf1 = (const float*)d_in[6];
    const float* Wf2 = (const float*)d_in[7];
    const float* bf2 = (const float*)d_in[8];
    const float* Wc1 = (const float*)d_in[9];
    const float* bc1 = (const float*)d_in[10];
    const float* Wc2 = (const float*)d_in[11];
    const float* bc2 = (const float*)d_in[12];
    const float* Wg1 = (const float*)d_in[13];
    const float* bg1 = (const float*)d_in[14];
    const float* Wg2 = (const float*)d_in[15];
    const float* bg2 = (const float*)d_in[16];
    float* out = (float*)d_out;

    const int smem_bytes = (ROWS * XP + 128 * WPP + ROWS * GP + ROWS * 4 + ROWS) * 4;
    cudaFuncSetAttribute(moe_kernel, cudaFuncAttributeMaxDynamicSharedMemorySize,
                         smem_bytes);

    int agg_blocks = (NCELLS * 32 + NTHREADS - 1) / NTHREADS;
    agg_kernel<<<agg_blocks, NTHREADS>>>(nb, cat);

    int moe_blocks = (NCELLS + ROWS - 1) / ROWS;
    moe_kernel<<<moe_blocks, NTHREADS, smem_bytes>>>(
        cur, Wl, bl, Wf1, bf1, Wf2, bf2, Wc1, bc1, Wc2, bc2,
        Wg1, bg1, Wg2, bg2, out, out_size);
}

// round 6
// speedup vs baseline: 1.5022x; 1.5022x over previous
#include <cuda_runtime.h>

#define NCELLS   19683
#define KNB      26
#define ROWS     72    // rows per CTA tile  -> grid 274 (single wave @ 2 CTA/SM)
#define NTHREADS 288   // 18 ty x 16 tx, 4 rows per thread
#define XP       132   // Xs row pitch (floats)
#define WPP      132   // Ws row pitch (floats)
#define GP       36    // Gs row pitch (floats), overlaid into Ws

// ---------------- scratch (device globals: allocation-free) ----------------
__device__ float g_mean_l[NCELLS * 64];
__device__ float g_mean_f[NCELLS * 64];
__device__ float g_mean_d[NCELLS * 64];
__device__ float g_act[NCELLS * 64];
__device__ int   g_flags[NCELLS];

typedef unsigned long long ull;

__device__ __forceinline__ ull pack2(float x, float y) {
    ull r; asm("mov.b64 %0, {%1,%2};" : "=l"(r) : "f"(x), "f"(y)); return r;
}
__device__ __forceinline__ float2 unpack2(ull v) {
    float2 r; asm("mov.b64 {%0,%1}, %2;" : "=f"(r.x), "=f"(r.y) : "l"(v)); return r;
}
__device__ __forceinline__ void ffma2(ull& acc, ull a, ull b) {
    asm("fma.rn.f32x2 %0, %1, %2, %0;" : "+l"(acc) : "l"(a), "l"(b));
}

// ---------------- kernel A: masked neighbor aggregation (branch-free) ------
// one warp per cell; lane handles cols {2l, 2l+1}; category masks via ballot
__global__ void agg_kernel(const float* __restrict__ nb, const int* __restrict__ cat) {
    int gw = (blockIdx.x * blockDim.x + threadIdx.x) >> 5;
    if (gw >= NCELLS) return;
    int lane = threadIdx.x & 31;
    const float* base = nb + (size_t)gw * (KNB * 64);
    int myc = (lane < KNB) ? cat[gw * KNB + lane] : -1;

    unsigned m0 = __ballot_sync(0xffffffffu, myc == 0);
    unsigned m1 = __ballot_sync(0xffffffffu, myc == 1);
    unsigned m2 = __ballot_sync(0xffffffffu, myc == 2);

    float2 s0 = {0.f, 0.f}, s1 = {0.f, 0.f}, s2 = {0.f, 0.f}, sa = {0.f, 0.f};
#pragma unroll
    for (int k = 0; k < KNB; k++) {
        float2 v = *(const float2*)(base + k * 64 + lane * 2);
        sa.x += v.x; sa.y += v.y;
        bool b0 = (m0 >> k) & 1u;
        bool b1 = (m1 >> k) & 1u;
        bool b2 = (m2 >> k) & 1u;
        s0.x += b0 ? v.x : 0.f;  s0.y += b0 ? v.y : 0.f;
        s1.x += b1 ? v.x : 0.f;  s1.y += b1 ? v.y : 0.f;
        s2.x += b2 ? v.x : 0.f;  s2.y += b2 ? v.y : 0.f;
    }
    int c0 = __popc(m0), c1 = __popc(m1), c2 = __popc(m2);
    float d0 = fmaxf((float)c0, 1.0f);
    float d1 = fmaxf((float)c1, 1.0f);
    float d2 = fmaxf((float)c2, 1.0f);
    int off = gw * 64 + lane * 2;
    *(float2*)(g_mean_l + off) = make_float2(s0.x / d0, s0.y / d0);
    *(float2*)(g_mean_f + off) = make_float2(s1.x / d1, s1.y / d1);
    *(float2*)(g_mean_d + off) = make_float2(s2.x / d2, s2.y / d2);
    *(float2*)(g_act    + off) = make_float2(sa.x / 26.0f, sa.y / 26.0f);
    if (lane == 0)
        g_flags[gw] = (c0 > 0 ? 1 : 0) | (c1 > 0 ? 2 : 0) | (c2 > 0 ? 4 : 0);
}

// ---------------- kernel B helpers ----------------
template <int NC>
__device__ __forceinline__ void loadW(const float* __restrict__ Wg, float* Ws, int tid) {
    constexpr int PR = NC / 4;  // float4 per row
    for (int i = tid; i < 128 * PR; i += NTHREADS) {
        int r = i / PR, c = i % PR;
        *(float4*)&Ws[r * WPP + c * 4] = ((const float4*)Wg)[i];
    }
}

// fill Xs = [L | R], both [row][64] row-major in global, rows base..base+ROWS-1
__device__ __forceinline__ void fillX(float* Xs, const float* __restrict__ L,
                                      const float* __restrict__ R,
                                      int tid, int base, int nrows) {
#pragma unroll
    for (int i = tid; i < ROWS * 32; i += NTHREADS) {  // ROWS*32 float4 (exact: 8 iters)
        int r = i >> 5;
        int c4 = i & 31;
        int gr = base + r;
        float4 v = make_float4(0.f, 0.f, 0.f, 0.f);
        if (r < nrows) {
            if (c4 < 16) v = *(const float4*)(L + (size_t)gr * 64 + (c4 << 2));
            else         v = *(const float4*)(R + (size_t)gr * 64 + ((c4 - 16) << 2));
        }
        *(float4*)&Xs[r * XP + (c4 << 2)] = v;
    }
}

// fill only right half of Xs from R
__device__ __forceinline__ void fillXright(float* Xs, const float* __restrict__ R,
                                           int tid, int base, int nrows) {
#pragma unroll
    for (int i = tid; i < ROWS * 16; i += NTHREADS) {  // exact: 4 iters
        int r = i >> 4;
        int c4 = i & 15;
        int gr = base + r;
        float4 v = make_float4(0.f, 0.f, 0.f, 0.f);
        if (r < nrows) v = *(const float4*)(R + (size_t)gr * 64 + (c4 << 2));
        *(float4*)&Xs[r * XP + 64 + (c4 << 2)] = v;
    }
}

// GEMM over K=128; fragment = 4 rows x TC cols per thread, packed f32x2 FMAs
template <int TC>
__device__ __forceinline__ void gemm128(const float* __restrict__ Xs,
                                        const float* __restrict__ Ws,
                                        int r0, int tx, ull (&acc)[4][TC / 2]) {
#pragma unroll
    for (int i = 0; i < 4; i++)
#pragma unroll
        for (int j = 0; j < TC / 2; j++) acc[i][j] = 0ULL;

#pragma unroll 2
    for (int k = 0; k < 128; k += 4) {
        float4 a[4];
#pragma unroll
        for (int i = 0; i < 4; i++) a[i] = *(const float4*)&Xs[(r0 + i) * XP + k];
#pragma unroll
        for (int kk = 0; kk < 4; kk++) {
            const float* bp = &Ws[(k + kk) * WPP + tx * TC];
            ull b[TC / 2];
            if constexpr (TC == 8) {
                ulonglong2 q0 = *(const ulonglong2*)bp;
                ulonglong2 q1 = *(const ulonglong2*)(bp + 4);
                b[0] = q0.x; b[1] = q0.y; b[2] = q1.x; b[3] = q1.y;
            } else if constexpr (TC == 4) {
                ulonglong2 q0 = *(const ulonglong2*)bp;
                b[0] = q0.x; b[1] = q0.y;
            } else {
                b[0] = *(const ull*)bp;
            }
#pragma unroll
            for (int i = 0; i < 4; i++) {
                float av = ((const float*)&a[i])[kk];
                ull ap = pack2(av, av);
#pragma unroll
                for (int j = 0; j < TC / 2; j++) ffma2(acc[i][j], ap, b[j]);
            }
        }
    }
}

// ---------------- kernel B: fused MoE MLP stack ----------------
__global__ void __launch_bounds__(NTHREADS, 2)
moe_kernel(const float* __restrict__ cur,
           const float* __restrict__ Wl,  const float* __restrict__ bl,
           const float* __restrict__ Wf1, const float* __restrict__ bf1,
           const float* __restrict__ Wf2, const float* __restrict__ bf2,
           const float* __restrict__ Wc1, const float* __restrict__ bc1,
           const float* __restrict__ Wc2, const float* __restrict__ bc2,
           const float* __restrict__ Wg1, const float* __restrict__ bg1,
           const float* __restrict__ Wg2, const float* __restrict__ bg2,
           float* __restrict__ out, int out_size) {
    extern __shared__ float sm[];
    float* Xs    = sm;                       // [ROWS][XP]
    float* Ws    = Xs + ROWS * XP;           // [128][WPP]  (Gs overlaid here)
    float* Gs    = Ws;                       // [ROWS][GP] overlay, used after gating GEMM
    float* sw    = Ws + 128 * WPP;           // [ROWS][4]
    int*   sflag = (int*)(sw + ROWS * 4);    // [ROWS]

    int tid  = threadIdx.x;
    int base = blockIdx.x * ROWS;
    int nrows = min(ROWS, NCELLS - base);

    int tx = tid & 15;          // 0..15 (column group)
    int ty = tid >> 4;          // 0..17 (row group)
    int r0 = ty * 4;

    if (tid < ROWS)
        sflag[tid] = (base + tid < NCELLS) ? g_flags[base + tid] : 0;

    // ================= gating =================
    fillX(Xs, cur, g_act, tid, base, nrows);
    loadW<32>(Wg1, Ws, tid);
    __syncthreads();
    ull ag[4][1];
    gemm128<2>(Xs, Ws, r0, tx, ag);
    __syncthreads();           // everyone done reading Ws -> safe to overlay Gs
    {
        float2 bg = *(const float2*)&bg1[tx * 2];
#pragma unroll
        for (int i = 0; i < 4; i++) {
            float2 v = unpack2(ag[i][0]);
            float2 o = make_float2(tanhf(v.x + bg.x), tanhf(v.y + bg.y));
            *(float2*)&Gs[(r0 + i) * GP + tx * 2] = o;
        }
    }
    __syncthreads();
    if (tid < ROWS) {
        int row = tid;
        float l0 = bg2[0], l1 = bg2[1], l2 = bg2[2];
#pragma unroll
        for (int k = 0; k < 32; k++) {
            float gv = Gs[row * GP + k];
            l0 += gv * Wg2[k * 3 + 0];
            l1 += gv * Wg2[k * 3 + 1];
            l2 += gv * Wg2[k * 3 + 2];
        }
        float m = fmaxf(l0, fmaxf(l1, l2));
        float e0 = expf(l0 - m), e1 = expf(l1 - m), e2 = expf(l2 - m);
        float inv = 1.0f / (e0 + e1 + e2);
        float w0 = e0 * inv, w1 = e1 * inv, w2 = e2 * inv;
        sw[row * 4 + 0] = w0; sw[row * 4 + 1] = w1; sw[row * 4 + 2] = w2;
        int gr = base + row;
        if (gr < NCELLS && out_size >= NCELLS * 67) {
            out[(size_t)NCELLS * 64 + (size_t)gr * 3 + 0] = w0;
            out[(size_t)NCELLS * 64 + (size_t)gr * 3 + 1] = w1;
            out[(size_t)NCELLS * 64 + (size_t)gr * 3 + 2] = w2;
        }
    }
    __syncthreads();           // Gs readers done -> Ws reusable

    float2 comb[4][2];

    // ================= local expert =================
    fillX(Xs, cur, g_mean_l, tid, base, nrows);
    loadW<64>(Wl, Ws, tid);
    __syncthreads();
    {
        ull al[4][2];
        gemm128<4>(Xs, Ws, r0, tx, al);
        float2 b0 = *(const float2*)&bl[tx * 4];
        float2 b1 = *(const float2*)&bl[tx * 4 + 2];
#pragma unroll
        for (int i = 0; i < 4; i++) {
            int row = r0 + i;
            float w0 = sw[row * 4 + 0];
            bool on = (sflag[row] & 1);
            float2 v0 = unpack2(al[i][0]);
            float2 v1 = unpack2(al[i][1]);
            comb[i][0].x = on ? w0 * tanhf(v0.x + b0.x) : 0.f;
            comb[i][0].y = on ? w0 * tanhf(v0.y + b0.y) : 0.f;
            comb[i][1].x = on ? w0 * tanhf(v1.x + b1.x) : 0.f;
            comb[i][1].y = on ? w0 * tanhf(v1.y + b1.y) : 0.f;
        }
    }
    __syncthreads();

    // ================= functional expert =================
    fillX(Xs, cur, g_mean_f, tid, base, nrows);
    loadW<128>(Wf1, Ws, tid);
    __syncthreads();
    {
        ull ah[4][4];
        gemm128<8>(Xs, Ws, r0, tx, ah);
        __syncthreads();  // all threads done reading Xs/Ws
        float4 b0 = *(const float4*)&bf1[tx * 8];
        float4 b1 = *(const float4*)&bf1[tx * 8 + 4];
#pragma unroll
        for (int i = 0; i < 4; i++) {
            float2 v0 = unpack2(ah[i][0]), v1 = unpack2(ah[i][1]);
            float2 v2 = unpack2(ah[i][2]), v3 = unpack2(ah[i][3]);
            float4 o0 = make_float4(tanhf(v0.x + b0.x), tanhf(v0.y + b0.y),
                                    tanhf(v1.x + b0.z), tanhf(v1.y + b0.w));
            float4 o1 = make_float4(tanhf(v2.x + b1.x), tanhf(v2.y + b1.y),
                                    tanhf(v3.x + b1.z), tanhf(v3.y + b1.w));
            *(float4*)&Xs[(r0 + i) * XP + tx * 8]     = o0;
            *(float4*)&Xs[(r0 + i) * XP + tx * 8 + 4] = o1;
        }
        loadW<64>(Wf2, Ws, tid);
        __syncthreads();
        ull af[4][2];
        gemm128<4>(Xs, Ws, r0, tx, af);
        float2 c0 = *(const float2*)&bf2[tx * 4];
        float2 c1 = *(const float2*)&bf2[tx * 4 + 2];
#pragma unroll
        for (int i = 0; i < 4; i++) {
            int row = r0 + i;
            float w1 = sw[row * 4 + 1];
            bool on = (sflag[row] & 2);
            float2 v0 = unpack2(af[i][0]);
            float2 v1 = unpack2(af[i][1]);
            comb[i][0].x += on ? w1 * tanhf(v0.x + c0.x) : 0.f;
            comb[i][0].y += on ? w1 * tanhf(v0.y + c0.y) : 0.f;
            comb[i][1].x += on ? w1 * tanhf(v1.x + c1.x) : 0.f;
            comb[i][1].y += on ? w1 * tanhf(v1.y + c1.y) : 0.f;
        }
    }
    __syncthreads();

    // ================= distant expert (CNF, 3 Euler steps) =================
    float2 x[4][2];
#pragma unroll
    for (int i = 0; i < 4; i++) {
        int gr = base + r0 + i;
        float4 cv = make_float4(0.f, 0.f, 0.f, 0.f);
        if (gr < NCELLS) cv = *(const float4*)(cur + (size_t)gr * 64 + tx * 4);
        x[i][0] = make_float2(cv.x, cv.y);
        x[i][1] = make_float2(cv.z, cv.w);
    }
    const float DT = 1.0f / 3.0f;
    for (int step = 0; step < 3; step++) {
        // Xs = [x | mean_d]
#pragma unroll
        for (int i = 0; i < 4; i++) {
            float4 xv = make_float4(x[i][0].x, x[i][0].y, x[i][1].x, x[i][1].y);
            *(float4*)&Xs[(r0 + i) * XP + tx * 4] = xv;
        }
        fillXright(Xs, g_mean_d, tid, base, nrows);
        loadW<128>(Wc1, Ws, tid);
        __syncthreads();
        ull av[4][4];
        gemm128<8>(Xs, Ws, r0, tx, av);
        __syncthreads();
        {
            float4 b0 = *(const float4*)&bc1[tx * 8];
            float4 b1 = *(const float4*)&bc1[tx * 8 + 4];
#pragma unroll
            for (int i = 0; i < 4; i++) {
                float2 v0 = unpack2(av[i][0]), v1 = unpack2(av[i][1]);
                float2 v2 = unpack2(av[i][2]), v3 = unpack2(av[i][3]);
                float4 o0 = make_float4(tanhf(v0.x + b0.x), tanhf(v0.y + b0.y),
                                        tanhf(v1.x + b0.z), tanhf(v1.y + b0.w));
                float4 o1 = make_float4(tanhf(v2.x + b1.x), tanhf(v2.y + b1.y),
                                        tanhf(v3.x + b1.z), tanhf(v3.y + b1.w));
                *(float4*)&Xs[(r0 + i) * XP + tx * 8]     = o0;
                *(float4*)&Xs[(r0 + i) * XP + tx * 8 + 4] = o1;
            }
        }
        loadW<64>(Wc2, Ws, tid);
        __syncthreads();
        ull ad[4][2];
        gemm128<4>(Xs, Ws, r0, tx, ad);
        {
            float2 c0 = *(const float2*)&bc2[tx * 4];
            float2 c1 = *(const float2*)&bc2[tx * 4 + 2];
#pragma unroll
            for (int i = 0; i < 4; i++) {
                float2 v0 = unpack2(ad[i][0]);
                float2 v1 = unpack2(ad[i][1]);
                x[i][0].x += DT * tanhf(v0.x + c0.x);
                x[i][0].y += DT * tanhf(v0.y + c0.y);
                x[i][1].x += DT * tanhf(v1.x + c1.x);
                x[i][1].y += DT * tanhf(v1.y + c1.y);
            }
        }
        __syncthreads();
    }
#pragma unroll
    for (int i = 0; i < 4; i++) {
        int row = r0 + i;
        float w2 = sw[row * 4 + 2];
        bool on = (sflag[row] & 4);
        comb[i][0].x += on ? w2 * x[i][0].x : 0.f;
        comb[i][0].y += on ? w2 * x[i][0].y : 0.f;
        comb[i][1].x += on ? w2 * x[i][1].x : 0.f;
        comb[i][1].y += on ? w2 * x[i][1].y : 0.f;
    }

    // ================= store combined =================
#pragma unroll
    for (int i = 0; i < 4; i++) {
        int gr = base + r0 + i;
        if (gr < NCELLS) {
            float4 o = make_float4(comb[i][0].x, comb[i][0].y,
                                   comb[i][1].x, comb[i][1].y);
            *(float4*)&out[(size_t)gr * 64 + tx * 4] = o;
        }
    }
}

// ---------------- launch ----------------
extern "C" void kernel_launch(void* const* d_in, const int* in_sizes, int n_in,
                              void* d_out, int out_size) {
    const float* cur = (const float*)d_in[0];
    const float* nb  = (const float*)d_in[1];
    const int*   cat = (const int*)d_in[2];
    const float* Wl  = (const float*)d_in[3];
    const float* bl  = (const float*)d_in[4];
    const float* Wf1 = (const float*)d_in[5];
    const float* bf1 = (const float*)d_in[6];
    const float* Wf2 = (const float*)d_in[7];
    const float* bf2 = (const float*)d_in[8];
    const float* Wc1 = (const float*)d_in[9];
    const float* bc1 = (const float*)d_in[10];
    const float* Wc2 = (const float*)d_in[11];
    const float* bc2 = (const float*)d_in[12];
    const float* Wg1 = (const float*)d_in[13];
    const float* bg1 = (const float*)d_in[14];
    const float* Wg2 = (const float*)d_in[15];
    const float* bg2 = (const float*)d_in[16];
    float* out = (float*)d_out;

    const int smem_bytes = (ROWS * XP + 128 * WPP + ROWS * 4 + ROWS) * 4;
    cudaFuncSetAttribute(moe_kernel, cudaFuncAttributeMaxDynamicSharedMemorySize,
                         smem_bytes);

    int agg_blocks = (NCELLS * 32 + 255) / 256;
    agg_kernel<<<agg_blocks, 256>>>(nb, cat);

    int moe_blocks = (NCELLS + ROWS - 1) / ROWS;   // 274 -> single wave at 2 CTA/SM
    moe_kernel<<<moe_blocks, NTHREADS, smem_bytes>>>(
        cur, Wl, bl, Wf1, bf1, Wf2, bf2, Wc1, bc1, Wc2, bc2,
        Wg1, bg1, Wg2, bg2, out, out_size);
}

// round 7
// speedup vs baseline: 1.6786x; 1.1174x over previous
#include <cuda_runtime.h>

#define NCELLS   19683
#define KNB      26
#define ROWS     72    // rows per CTA tile  -> grid 274 (single wave @ 2 CTA/SM)
#define NTHREADS 128   // 16 tx x 8 ty, 9 rows per thread
#define RPT      9     // rows per thread
#define XP       132   // Xs row pitch (floats)
#define WPP      132   // Ws row pitch (floats)
#define GP       36    // Gs row pitch (floats), overlaid into Ws

// ---------------- scratch (device globals: allocation-free) ----------------
__device__ float g_mean_l[NCELLS * 64];
__device__ float g_mean_f[NCELLS * 64];
__device__ float g_mean_d[NCELLS * 64];
__device__ float g_act[NCELLS * 64];
__device__ int   g_flags[NCELLS];

typedef unsigned long long ull;

__device__ __forceinline__ ull pack2(float x, float y) {
    ull r; asm("mov.b64 %0, {%1,%2};" : "=l"(r) : "f"(x), "f"(y)); return r;
}
__device__ __forceinline__ float2 unpack2(ull v) {
    float2 r; asm("mov.b64 {%0,%1}, %2;" : "=f"(r.x), "=f"(r.y) : "l"(v)); return r;
}
__device__ __forceinline__ void ffma2(ull& acc, ull a, ull b) {
    asm("fma.rn.f32x2 %0, %1, %2, %0;" : "+l"(acc) : "l"(a), "l"(b));
}

// ---------------- kernel A: masked neighbor aggregation (branch-free) ------
__global__ void agg_kernel(const float* __restrict__ nb, const int* __restrict__ cat) {
    int gw = (blockIdx.x * blockDim.x + threadIdx.x) >> 5;
    if (gw >= NCELLS) return;
    int lane = threadIdx.x & 31;
    const float* base = nb + (size_t)gw * (KNB * 64);
    int myc = (lane < KNB) ? cat[gw * KNB + lane] : -1;

    unsigned m0 = __ballot_sync(0xffffffffu, myc == 0);
    unsigned m1 = __ballot_sync(0xffffffffu, myc == 1);
    unsigned m2 = __ballot_sync(0xffffffffu, myc == 2);

    float2 s0 = {0.f, 0.f}, s1 = {0.f, 0.f}, s2 = {0.f, 0.f}, sa = {0.f, 0.f};
#pragma unroll
    for (int k = 0; k < KNB; k++) {
        float2 v = *(const float2*)(base + k * 64 + lane * 2);
        sa.x += v.x; sa.y += v.y;
        bool b0 = (m0 >> k) & 1u;
        bool b1 = (m1 >> k) & 1u;
        bool b2 = (m2 >> k) & 1u;
        s0.x += b0 ? v.x : 0.f;  s0.y += b0 ? v.y : 0.f;
        s1.x += b1 ? v.x : 0.f;  s1.y += b1 ? v.y : 0.f;
        s2.x += b2 ? v.x : 0.f;  s2.y += b2 ? v.y : 0.f;
    }
    int c0 = __popc(m0), c1 = __popc(m1), c2 = __popc(m2);
    float d0 = fmaxf((float)c0, 1.0f);
    float d1 = fmaxf((float)c1, 1.0f);
    float d2 = fmaxf((float)c2, 1.0f);
    int off = gw * 64 + lane * 2;
    *(float2*)(g_mean_l + off) = make_float2(s0.x / d0, s0.y / d0);
    *(float2*)(g_mean_f + off) = make_float2(s1.x / d1, s1.y / d1);
    *(float2*)(g_mean_d + off) = make_float2(s2.x / d2, s2.y / d2);
    *(float2*)(g_act    + off) = make_float2(sa.x / 26.0f, sa.y / 26.0f);
    if (lane == 0)
        g_flags[gw] = (c0 > 0 ? 1 : 0) | (c1 > 0 ? 2 : 0) | (c2 > 0 ? 4 : 0);
}

// ---------------- kernel B helpers ----------------
template <int NC>
__device__ __forceinline__ void loadW(const float* __restrict__ Wg, float* Ws, int tid) {
    constexpr int PR = NC / 4;  // float4 per row
    for (int i = tid; i < 128 * PR; i += NTHREADS) {
        int r = i / PR, c = i % PR;
        *(float4*)&Ws[r * WPP + c * 4] = ((const float4*)Wg)[i];
    }
}

// fill Xs = [L | R]
__device__ __forceinline__ void fillX(float* Xs, const float* __restrict__ L,
                                      const float* __restrict__ R,
                                      int tid, int base, int nrows) {
#pragma unroll
    for (int i = tid; i < ROWS * 32; i += NTHREADS) {  // 18 iters
        int r = i >> 5;
        int c4 = i & 31;
        int gr = base + r;
        float4 v = make_float4(0.f, 0.f, 0.f, 0.f);
        if (r < nrows) {
            if (c4 < 16) v = *(const float4*)(L + (size_t)gr * 64 + (c4 << 2));
            else         v = *(const float4*)(R + (size_t)gr * 64 + ((c4 - 16) << 2));
        }
        *(float4*)&Xs[r * XP + (c4 << 2)] = v;
    }
}

// fill only right half of Xs from R (left half assumed already valid)
__device__ __forceinline__ void fillXright(float* Xs, const float* __restrict__ R,
                                           int tid, int base, int nrows) {
#pragma unroll
    for (int i = tid; i < ROWS * 16; i += NTHREADS) {  // 9 iters
        int r = i >> 4;
        int c4 = i & 15;
        int gr = base + r;
        float4 v = make_float4(0.f, 0.f, 0.f, 0.f);
        if (r < nrows) v = *(const float4*)(R + (size_t)gr * 64 + (c4 << 2));
        *(float4*)&Xs[r * XP + 64 + (c4 << 2)] = v;
    }
}

// GEMM over K=128; fragment = RPT rows x TC cols per thread, packed f32x2 FMAs
template <int TC>
__device__ __forceinline__ void gemm128(const float* __restrict__ Xs,
                                        const float* __restrict__ Ws,
                                        int r0, int tx, ull (&acc)[RPT][TC / 2]) {
#pragma unroll
    for (int i = 0; i < RPT; i++)
#pragma unroll
        for (int j = 0; j < TC / 2; j++) acc[i][j] = 0ULL;

#pragma unroll 2
    for (int k = 0; k < 128; k += 4) {
        float4 a[RPT];
#pragma unroll
        for (int i = 0; i < RPT; i++) a[i] = *(const float4*)&Xs[(r0 + i) * XP + k];
#pragma unroll
        for (int kk = 0; kk < 4; kk++) {
            const float* bp = &Ws[(k + kk) * WPP + tx * TC];
            ull b[TC / 2];
            if constexpr (TC == 8) {
                ulonglong2 q0 = *(const ulonglong2*)bp;
                ulonglong2 q1 = *(const ulonglong2*)(bp + 4);
                b[0] = q0.x; b[1] = q0.y; b[2] = q1.x; b[3] = q1.y;
            } else if constexpr (TC == 4) {
                ulonglong2 q0 = *(const ulonglong2*)bp;
                b[0] = q0.x; b[1] = q0.y;
            } else {
                b[0] = *(const ull*)bp;
            }
#pragma unroll
            for (int i = 0; i < RPT; i++) {
                float av = ((const float*)&a[i])[kk];
                ull ap = pack2(av, av);
#pragma unroll
                for (int j = 0; j < TC / 2; j++) ffma2(acc[i][j], ap, b[j]);
            }
        }
    }
}

// ---------------- kernel B: fused MoE MLP stack ----------------
__global__ void __launch_bounds__(NTHREADS, 2)
moe_kernel(const float* __restrict__ cur,
           const float* __restrict__ Wl,  const float* __restrict__ bl,
           const float* __restrict__ Wf1, const float* __restrict__ bf1,
           const float* __restrict__ Wf2, const float* __restrict__ bf2,
           const float* __restrict__ Wc1, const float* __restrict__ bc1,
           const float* __restrict__ Wc2, const float* __restrict__ bc2,
           const float* __restrict__ Wg1, const float* __restrict__ bg1,
           const float* __restrict__ Wg2, const float* __restrict__ bg2,
           float* __restrict__ out, int out_size) {
    extern __shared__ float sm[];
    float* Xs    = sm;                       // [ROWS][XP]
    float* Ws    = Xs + ROWS * XP;           // [128][WPP]  (Gs overlaid here)
    float* Gs    = Ws;                       // [ROWS][GP] overlay
    float* sw    = Ws + 128 * WPP;           // [ROWS][4]
    int*   sflag = (int*)(sw + ROWS * 4);    // [ROWS]

    int tid  = threadIdx.x;
    int base = blockIdx.x * ROWS;
    int nrows = min(ROWS, NCELLS - base);

    int tx = tid & 15;          // 0..15 (column group)
    int ty = tid >> 4;          // 0..7  (row group)
    int r0 = ty * RPT;

    if (tid < ROWS)
        sflag[tid] = (base + tid < NCELLS) ? g_flags[base + tid] : 0;

    // ================= gating =================
    fillX(Xs, cur, g_act, tid, base, nrows);
    loadW<32>(Wg1, Ws, tid);
    __syncthreads();
    ull ag[RPT][1];
    gemm128<2>(Xs, Ws, r0, tx, ag);
    __syncthreads();           // done reading Ws -> safe to overlay Gs
    {
        float2 bg = *(const float2*)&bg1[tx * 2];
#pragma unroll
        for (int i = 0; i < RPT; i++) {
            float2 v = unpack2(ag[i][0]);
            float2 o = make_float2(tanhf(v.x + bg.x), tanhf(v.y + bg.y));
            *(float2*)&Gs[(r0 + i) * GP + tx * 2] = o;
        }
    }
    __syncthreads();
    if (tid < ROWS) {
        int row = tid;
        float l0 = bg2[0], l1 = bg2[1], l2 = bg2[2];
#pragma unroll
        for (int k = 0; k < 32; k++) {
            float gv = Gs[row * GP + k];
            l0 += gv * Wg2[k * 3 + 0];
            l1 += gv * Wg2[k * 3 + 1];
            l2 += gv * Wg2[k * 3 + 2];
        }
        float m = fmaxf(l0, fmaxf(l1, l2));
        float e0 = expf(l0 - m), e1 = expf(l1 - m), e2 = expf(l2 - m);
        float inv = 1.0f / (e0 + e1 + e2);
        float w0 = e0 * inv, w1 = e1 * inv, w2 = e2 * inv;
        sw[row * 4 + 0] = w0; sw[row * 4 + 1] = w1; sw[row * 4 + 2] = w2;
        int gr = base + row;
        if (gr < NCELLS && out_size >= NCELLS * 67) {
            out[(size_t)NCELLS * 64 + (size_t)gr * 3 + 0] = w0;
            out[(size_t)NCELLS * 64 + (size_t)gr * 3 + 1] = w1;
            out[(size_t)NCELLS * 64 + (size_t)gr * 3 + 2] = w2;
        }
    }
    __syncthreads();           // Gs readers done -> Ws reusable

    float2 comb[RPT][2];

    // ================= local expert =================
    // left half of Xs still holds cur; only refresh right half
    fillXright(Xs, g_mean_l, tid, base, nrows);
    loadW<64>(Wl, Ws, tid);
    __syncthreads();
    {
        ull al[RPT][2];
        gemm128<4>(Xs, Ws, r0, tx, al);
        float2 b0 = *(const float2*)&bl[tx * 4];
        float2 b1 = *(const float2*)&bl[tx * 4 + 2];
#pragma unroll
        for (int i = 0; i < RPT; i++) {
            int row = r0 + i;
            float w0 = sw[row * 4 + 0];
            bool on = (sflag[row] & 1);
            float2 v0 = unpack2(al[i][0]);
            float2 v1 = unpack2(al[i][1]);
            comb[i][0].x = on ? w0 * tanhf(v0.x + b0.x) : 0.f;
            comb[i][0].y = on ? w0 * tanhf(v0.y + b0.y) : 0.f;
            comb[i][1].x = on ? w0 * tanhf(v1.x + b1.x) : 0.f;
            comb[i][1].y = on ? w0 * tanhf(v1.y + b1.y) : 0.f;
        }
    }
    __syncthreads();

    // ================= functional expert =================
    // left half of Xs still holds cur; only refresh right half
    fillXright(Xs, g_mean_f, tid, base, nrows);
    loadW<128>(Wf1, Ws, tid);
    __syncthreads();
    {
        ull ah[RPT][4];
        gemm128<8>(Xs, Ws, r0, tx, ah);
        __syncthreads();  // all threads done reading Xs/Ws
        float4 b0 = *(const float4*)&bf1[tx * 8];
        float4 b1 = *(const float4*)&bf1[tx * 8 + 4];
#pragma unroll
        for (int i = 0; i < RPT; i++) {
            float2 v0 = unpack2(ah[i][0]), v1 = unpack2(ah[i][1]);
            float2 v2 = unpack2(ah[i][2]), v3 = unpack2(ah[i][3]);
            float4 o0 = make_float4(tanhf(v0.x + b0.x), tanhf(v0.y + b0.y),
                                    tanhf(v1.x + b0.z), tanhf(v1.y + b0.w));
            float4 o1 = make_float4(tanhf(v2.x + b1.x), tanhf(v2.y + b1.y),
                                    tanhf(v3.x + b1.z), tanhf(v3.y + b1.w));
            *(float4*)&Xs[(r0 + i) * XP + tx * 8]     = o0;
            *(float4*)&Xs[(r0 + i) * XP + tx * 8 + 4] = o1;
        }
        loadW<64>(Wf2, Ws, tid);
        __syncthreads();
        ull af[RPT][2];
        gemm128<4>(Xs, Ws, r0, tx, af);
        float2 c0 = *(const float2*)&bf2[tx * 4];
        float2 c1 = *(const float2*)&bf2[tx * 4 + 2];
#pragma unroll
        for (int i = 0; i < RPT; i++) {
            int row = r0 + i;
            float w1 = sw[row * 4 + 1];
            bool on = (sflag[row] & 2);
            float2 v0 = unpack2(af[i][0]);
            float2 v1 = unpack2(af[i][1]);
            comb[i][0].x += on ? w1 * tanhf(v0.x + c0.x) : 0.f;
            comb[i][0].y += on ? w1 * tanhf(v0.y + c0.y) : 0.f;
            comb[i][1].x += on ? w1 * tanhf(v1.x + c1.x) : 0.f;
            comb[i][1].y += on ? w1 * tanhf(v1.y + c1.y) : 0.f;
        }
    }
    __syncthreads();

    // ================= distant expert (CNF, 3 Euler steps) =================
    float2 x[RPT][2];
#pragma unroll
    for (int i = 0; i < RPT; i++) {
        int gr = base + r0 + i;
        float4 cv = make_float4(0.f, 0.f, 0.f, 0.f);
        if (gr < NCELLS) cv = *(const float4*)(cur + (size_t)gr * 64 + tx * 4);
        x[i][0] = make_float2(cv.x, cv.y);
        x[i][1] = make_float2(cv.z, cv.w);
    }
    const float DT = 1.0f / 3.0f;
    for (int step = 0; step < 3; step++) {
        // Xs = [x | mean_d]
#pragma unroll
        for (int i = 0; i < RPT; i++) {
            float4 xv = make_float4(x[i][0].x, x[i][0].y, x[i][1].x, x[i][1].y);
            *(float4*)&Xs[(r0 + i) * XP + tx * 4] = xv;
        }
        fillXright(Xs, g_mean_d, tid, base, nrows);
        loadW<128>(Wc1, Ws, tid);
        __syncthreads();
        ull av[RPT][4];
        gemm128<8>(Xs, Ws, r0, tx, av);
        __syncthreads();
        {
            float4 b0 = *(const float4*)&bc1[tx * 8];
            float4 b1 = *(const float4*)&bc1[tx * 8 + 4];
#pragma unroll
            for (int i = 0; i < RPT; i++) {
                float2 v0 = unpack2(av[i][0]), v1 = unpack2(av[i][1]);
                float2 v2 = unpack2(av[i][2]), v3 = unpack2(av[i][3]);
                float4 o0 = make_float4(tanhf(v0.x + b0.x), tanhf(v0.y + b0.y),
                                        tanhf(v1.x + b0.z), tanhf(v1.y + b0.w));
                float4 o1 = make_float4(tanhf(v2.x + b1.x), tanhf(v2.y + b1.y),
                                        tanhf(v3.x + b1.z), tanhf(v3.y + b1.w));
                *(float4*)&Xs[(r0 + i) * XP + tx * 8]     = o0;
                *(float4*)&Xs[(r0 + i) * XP + tx * 8 + 4] = o1;
            }
        }
        loadW<64>(Wc2, Ws, tid);
        __syncthreads();
        ull ad[RPT][2];
        gemm128<4>(Xs, Ws, r0, tx, ad);
        {
            float2 c0 = *(const float2*)&bc2[tx * 4];
            float2 c1 = *(const float2*)&bc2[tx * 4 + 2];
#pragma unroll
            for (int i = 0; i < RPT; i++) {
                float2 v0 = unpack2(ad[i][0]);
                float2 v1 = unpack2(ad[i][1]);
                x[i][0].x += DT * tanhf(v0.x + c0.x);
                x[i][0].y += DT * tanhf(v0.y + c0.y);
                x[i][1].x += DT * tanhf(v1.x + c1.x);
                x[i][1].y += DT * tanhf(v1.y + c1.y);
            }
        }
        __syncthreads();
    }
#pragma unroll
    for (int i = 0; i < RPT; i++) {
        int row = r0 + i;
        float w2 = sw[row * 4 + 2];
        bool on = (sflag[row] & 4);
        comb[i][0].x += on ? w2 * x[i][0].x : 0.f;
        comb[i][0].y += on ? w2 * x[i][0].y : 0.f;
        comb[i][1].x += on ? w2 * x[i][1].x : 0.f;
        comb[i][1].y += on ? w2 * x[i][1].y : 0.f;
    }

    // ================= store combined =================
#pragma unroll
    for (int i = 0; i < RPT; i++) {
        int gr = base + r0 + i;
        if (gr < NCELLS) {
            float4 o = make_float4(comb[i][0].x, comb[i][0].y,
                                   comb[i][1].x, comb[i][1].y);
            *(float4*)&out[(size_t)gr * 64 + tx * 4] = o;
        }
    }
}

// ---------------- launch ----------------
extern "C" void kernel_launch(void* const* d_in, const int* in_sizes, int n_in,
                              void* d_out, int out_size) {
    const float* cur = (const float*)d_in[0];
    const float* nb  = (const float*)d_in[1];
    const int*   cat = (const int*)d_in[2];
    const float* Wl  = (const float*)d_in[3];
    const float* bl  = (const float*)d_in[4];
    const float* Wf1 = (const float*)d_in[5];
    const float* bf1 = (const float*)d_in[6];
    const float* Wf2 = (const float*)d_in[7];
    const float* bf2 = (const float*)d_in[8];
    const float* Wc1 = (const float*)d_in[9];
    const float* bc1 = (const float*)d_in[10];
    const float* Wc2 = (const float*)d_in[11];
    const float* bc2 = (const float*)d_in[12];
    const float* Wg1 = (const float*)d_in[13];
    const float* bg1 = (const float*)d_in[14];
    const float* Wg2 = (const float*)d_in[15];
    const float* bg2 = (const float*)d_in[16];
    float* out = (float*)d_out;

    const int smem_bytes = (ROWS * XP + 128 * WPP + ROWS * 4 + ROWS) * 4;
    cudaFuncSetAttribute(moe_kernel, cudaFuncAttributeMaxDynamicSharedMemorySize,
                         smem_bytes);

    int agg_blocks = (NCELLS * 32 + 255) / 256;
    agg_kernel<<<agg_blocks, 256>>>(nb, cat);

    int moe_blocks = (NCELLS + ROWS - 1) / ROWS;   // 274 -> single wave at 2 CTA/SM
    moe_kernel<<<moe_blocks, NTHREADS, smem_bytes>>>(
        cur, Wl, bl, Wf1, bf1, Wf2, bf2, Wc1, bc1, Wc2, bc2,
        Wg1, bg1, Wg2, bg2, out, out_size);
}

// round 9
// speedup vs baseline: 1.7241x; 1.0271x over previous
#include <cuda_runtime.h>

#define NCELLS   19683
#define KNB      26
#define ROWS     72    // rows per CTA tile  -> grid 274 (single wave @ 2 CTA/SM)
#define NTHREADS 192   // 16 tx x 12 ty, 6 rows per thread
#define RPT      6     // rows per thread
#define XP       132   // Xs row pitch (floats)
#define WPP      132   // Ws row pitch (floats)
#define GP       36    // Gs row pitch (floats), overlaid into Ws

// ---------------- scratch (device globals: allocation-free) ----------------
__device__ float g_mean_l[NCELLS * 64];
__device__ float g_mean_f[NCELLS * 64];
__device__ float g_mean_d[NCELLS * 64];
__device__ float g_act[NCELLS * 64];
__device__ int   g_flags[NCELLS];

typedef unsigned long long ull;

__device__ __forceinline__ ull pack2(float x, float y) {
    ull r; asm("mov.b64 %0, {%1,%2};" : "=l"(r) : "f"(x), "f"(y)); return r;
}
__device__ __forceinline__ float2 unpack2(ull v) {
    float2 r; asm("mov.b64 {%0,%1}, %2;" : "=f"(r.x), "=f"(r.y) : "l"(v)); return r;
}
__device__ __forceinline__ void ffma2(ull& acc, ull a, ull b) {
    asm("fma.rn.f32x2 %0, %1, %2, %0;" : "+l"(acc) : "l"(a), "l"(b));
}

// ---------------- kernel A: masked neighbor aggregation (branch-free) ------
__global__ void agg_kernel(const float* __restrict__ nb, const int* __restrict__ cat) {
    int gw = (blockIdx.x * blockDim.x + threadIdx.x) >> 5;
    if (gw >= NCELLS) return;
    int lane = threadIdx.x & 31;
    const float* base = nb + (size_t)gw * (KNB * 64);
    int myc = (lane < KNB) ? cat[gw * KNB + lane] : -1;

    unsigned m0 = __ballot_sync(0xffffffffu, myc == 0);
    unsigned m1 = __ballot_sync(0xffffffffu, myc == 1);
    unsigned m2 = __ballot_sync(0xffffffffu, myc == 2);

    float2 s0 = {0.f, 0.f}, s1 = {0.f, 0.f}, s2 = {0.f, 0.f}, sa = {0.f, 0.f};
#pragma unroll
    for (int k = 0; k < KNB; k++) {
        float2 v = *(const float2*)(base + k * 64 + lane * 2);
        sa.x += v.x; sa.y += v.y;
        bool b0 = (m0 >> k) & 1u;
        bool b1 = (m1 >> k) & 1u;
        bool b2 = (m2 >> k) & 1u;
        s0.x += b0 ? v.x : 0.f;  s0.y += b0 ? v.y : 0.f;
        s1.x += b1 ? v.x : 0.f;  s1.y += b1 ? v.y : 0.f;
        s2.x += b2 ? v.x : 0.f;  s2.y += b2 ? v.y : 0.f;
    }
    int c0 = __popc(m0), c1 = __popc(m1), c2 = __popc(m2);
    float d0 = fmaxf((float)c0, 1.0f);
    float d1 = fmaxf((float)c1, 1.0f);
    float d2 = fmaxf((float)c2, 1.0f);
    int off = gw * 64 + lane * 2;
    *(float2*)(g_mean_l + off) = make_float2(s0.x / d0, s0.y / d0);
    *(float2*)(g_mean_f + off) = make_float2(s1.x / d1, s1.y / d1);
    *(float2*)(g_mean_d + off) = make_float2(s2.x / d2, s2.y / d2);
    *(float2*)(g_act    + off) = make_float2(sa.x / 26.0f, sa.y / 26.0f);
    if (lane == 0)
        g_flags[gw] = (c0 > 0 ? 1 : 0) | (c1 > 0 ? 2 : 0) | (c2 > 0 ? 4 : 0);
}

// ---------------- kernel B helpers ----------------
template <int NC>
__device__ __forceinline__ void loadW(const float* __restrict__ Wg, float* Ws, int tid) {
    constexpr int PR = NC / 4;  // float4 per row
    for (int i = tid; i < 128 * PR; i += NTHREADS) {
        int r = i / PR, c = i % PR;
        *(float4*)&Ws[r * WPP + c * 4] = ((const float4*)Wg)[i];
    }
}

// fill Xs = [L | R]
__device__ __forceinline__ void fillX(float* Xs, const float* __restrict__ L,
                                      const float* __restrict__ R,
                                      int tid, int base, int nrows) {
#pragma unroll
    for (int i = tid; i < ROWS * 32; i += NTHREADS) {  // 12 iters exact
        int r = i >> 5;
        int c4 = i & 31;
        int gr = base + r;
        float4 v = make_float4(0.f, 0.f, 0.f, 0.f);
        if (r < nrows) {
            if (c4 < 16) v = *(const float4*)(L + (size_t)gr * 64 + (c4 << 2));
            else         v = *(const float4*)(R + (size_t)gr * 64 + ((c4 - 16) << 2));
        }
        *(float4*)&Xs[r * XP + (c4 << 2)] = v;
    }
}

// fill only right half of Xs from R (left half assumed already valid)
__device__ __forceinline__ void fillXright(float* Xs, const float* __restrict__ R,
                                           int tid, int base, int nrows) {
#pragma unroll
    for (int i = tid; i < ROWS * 16; i += NTHREADS) {  // 6 iters exact
        int r = i >> 4;
        int c4 = i & 15;
        int gr = base + r;
        float4 v = make_float4(0.f, 0.f, 0.f, 0.f);
        if (r < nrows) v = *(const float4*)(R + (size_t)gr * 64 + (c4 << 2));
        *(float4*)&Xs[r * XP + 64 + (c4 << 2)] = v;
    }
}

// GEMM over K=128; fragment = RPT rows x TC cols per thread, packed f32x2 FMAs
template <int TC>
__device__ __forceinline__ void gemm128(const float* __restrict__ Xs,
                                        const float* __restrict__ Ws,
                                        int r0, int tx, ull (&acc)[RPT][TC / 2]) {
#pragma unroll
    for (int i = 0; i < RPT; i++)
#pragma unroll
        for (int j = 0; j < TC / 2; j++) acc[i][j] = 0ULL;

#pragma unroll 2
    for (int k = 0; k < 128; k += 4) {
        float4 a[RPT];
#pragma unroll
        for (int i = 0; i < RPT; i++) a[i] = *(const float4*)&Xs[(r0 + i) * XP + k];
#pragma unroll
        for (int kk = 0; kk < 4; kk++) {
            const float* bp = &Ws[(k + kk) * WPP + tx * TC];
            ull b[TC / 2];
            if constexpr (TC == 8) {
                ulonglong2 q0 = *(const ulonglong2*)bp;
                ulonglong2 q1 = *(const ulonglong2*)(bp + 4);
                b[0] = q0.x; b[1] = q0.y; b[2] = q1.x; b[3] = q1.y;
            } else if constexpr (TC == 4) {
                ulonglong2 q0 = *(const ulonglong2*)bp;
                b[0] = q0.x; b[1] = q0.y;
            } else {
                b[0] = *(const ull*)bp;
            }
#pragma unroll
            for (int i = 0; i < RPT; i++) {
                float av = ((const float*)&a[i])[kk];
                ull ap = pack2(av, av);
#pragma unroll
                for (int j = 0; j < TC / 2; j++) ffma2(acc[i][j], ap, b[j]);
            }
        }
    }
}

// ---------------- kernel B: fused MoE MLP stack ----------------
__global__ void __launch_bounds__(NTHREADS, 2)
moe_kernel(const float* __restrict__ cur,
           const float* __restrict__ Wl,  const float* __restrict__ bl,
           const float* __restrict__ Wf1, const float* __restrict__ bf1,
           const float* __restrict__ Wf2, const float* __restrict__ bf2,
           const float* __restrict__ Wc1, const float* __restrict__ bc1,
           const float* __restrict__ Wc2, const float* __restrict__ bc2,
           const float* __restrict__ Wg1, const float* __restrict__ bg1,
           const float* __restrict__ Wg2, const float* __restrict__ bg2,
           float* __restrict__ out, int out_size) {
    extern __shared__ float sm[];
    float* Xs    = sm;                       // [ROWS][XP]
    float* Ws    = Xs + ROWS * XP;           // [128][WPP]  (Gs overlaid here)
    float* Gs    = Ws;                       // [ROWS][GP] overlay
    float* sw    = Ws + 128 * WPP;           // [ROWS][4]
    int*   sflag = (int*)(sw + ROWS * 4);    // [ROWS]

    int tid  = threadIdx.x;
    int base = blockIdx.x * ROWS;
    int nrows = min(ROWS, NCELLS - base);

    int tx = tid & 15;          // 0..15 (column group)
    int ty = tid >> 4;          // 0..11 (row group)
    int r0 = ty * RPT;

    if (tid < ROWS)
        sflag[tid] = (base + tid < NCELLS) ? g_flags[base + tid] : 0;

    // ================= gating =================
    fillX(Xs, cur, g_act, tid, base, nrows);
    loadW<32>(Wg1, Ws, tid);
    __syncthreads();
    ull ag[RPT][1];
    gemm128<2>(Xs, Ws, r0, tx, ag);
    __syncthreads();           // done reading Ws -> safe to overlay Gs
    {
        float2 bg = *(const float2*)&bg1[tx * 2];
#pragma unroll
        for (int i = 0; i < RPT; i++) {
            float2 v = unpack2(ag[i][0]);
            float2 o = make_float2(tanhf(v.x + bg.x), tanhf(v.y + bg.y));
            *(float2*)&Gs[(r0 + i) * GP + tx * 2] = o;
        }
    }
    __syncthreads();
    if (tid < ROWS) {
        int row = tid;
        float l0 = bg2[0], l1 = bg2[1], l2 = bg2[2];
#pragma unroll
        for (int k = 0; k < 32; k++) {
            float gv = Gs[row * GP + k];
            l0 += gv * Wg2[k * 3 + 0];
            l1 += gv * Wg2[k * 3 + 1];
            l2 += gv * Wg2[k * 3 + 2];
        }
        float m = fmaxf(l0, fmaxf(l1, l2));
        float e0 = expf(l0 - m), e1 = expf(l1 - m), e2 = expf(l2 - m);
        float inv = 1.0f / (e0 + e1 + e2);
        float w0 = e0 * inv, w1 = e1 * inv, w2 = e2 * inv;
        sw[row * 4 + 0] = w0; sw[row * 4 + 1] = w1; sw[row * 4 + 2] = w2;
        int gr = base + row;
        if (gr < NCELLS && out_size >= NCELLS * 67) {
            out[(size_t)NCELLS * 64 + (size_t)gr * 3 + 0] = w0;
            out[(size_t)NCELLS * 64 + (size_t)gr * 3 + 1] = w1;
            out[(size_t)NCELLS * 64 + (size_t)gr * 3 + 2] = w2;
        }
    }
    __syncthreads();           // Gs readers done -> Ws reusable

    float2 comb[RPT][2];

    // ================= local expert =================
    // left half of Xs still holds cur; only refresh right half
    fillXright(Xs, g_mean_l, tid, base, nrows);
    loadW<64>(Wl, Ws, tid);
    __syncthreads();
    {
        ull al[RPT][2];
        gemm128<4>(Xs, Ws, r0, tx, al);
        float2 b0 = *(const float2*)&bl[tx * 4];
        float2 b1 = *(const float2*)&bl[tx * 4 + 2];
#pragma unroll
        for (int i = 0; i < RPT; i++) {
            int row = r0 + i;
            float w0 = sw[row * 4 + 0];
            bool on = (sflag[row] & 1);
            float2 v0 = unpack2(al[i][0]);
            float2 v1 = unpack2(al[i][1]);
            comb[i][0].x = on ? w0 * tanhf(v0.x + b0.x) : 0.f;
            comb[i][0].y = on ? w0 * tanhf(v0.y + b0.y) : 0.f;
            comb[i][1].x = on ? w0 * tanhf(v1.x + b1.x) : 0.f;
            comb[i][1].y = on ? w0 * tanhf(v1.y + b1.y) : 0.f;
        }
    }
    __syncthreads();

    // ================= functional expert =================
    // left half of Xs still holds cur; only refresh right half
    fillXright(Xs, g_mean_f, tid, base, nrows);
    loadW<128>(Wf1, Ws, tid);
    __syncthreads();
    {
        ull ah[RPT][4];
        gemm128<8>(Xs, Ws, r0, tx, ah);
        __syncthreads();  // all threads done reading Xs/Ws
        float4 b0 = *(const float4*)&bf1[tx * 8];
        float4 b1 = *(const float4*)&bf1[tx * 8 + 4];
#pragma unroll
        for (int i = 0; i < RPT; i++) {
            float2 v0 = unpack2(ah[i][0]), v1 = unpack2(ah[i][1]);
            float2 v2 = unpack2(ah[i][2]), v3 = unpack2(ah[i][3]);
            float4 o0 = make_float4(tanhf(v0.x + b0.x), tanhf(v0.y + b0.y),
                                    tanhf(v1.x + b0.z), tanhf(v1.y + b0.w));
            float4 o1 = make_float4(tanhf(v2.x + b1.x), tanhf(v2.y + b1.y),
                                    tanhf(v3.x + b1.z), tanhf(v3.y + b1.w));
            *(float4*)&Xs[(r0 + i) * XP + tx * 8]     = o0;
            *(float4*)&Xs[(r0 + i) * XP + tx * 8 + 4] = o1;
        }
        loadW<64>(Wf2, Ws, tid);
        __syncthreads();
        ull af[RPT][2];
        gemm128<4>(Xs, Ws, r0, tx, af);
        float2 c0 = *(const float2*)&bf2[tx * 4];
        float2 c1 = *(const float2*)&bf2[tx * 4 + 2];
#pragma unroll
        for (int i = 0; i < RPT; i++) {
            int row = r0 + i;
            float w1 = sw[row * 4 + 1];
            bool on = (sflag[row] & 2);
            float2 v0 = unpack2(af[i][0]);
            float2 v1 = unpack2(af[i][1]);
            comb[i][0].x += on ? w1 * tanhf(v0.x + c0.x) : 0.f;
            comb[i][0].y += on ? w1 * tanhf(v0.y + c0.y) : 0.f;
            comb[i][1].x += on ? w1 * tanhf(v1.x + c1.x) : 0.f;
            comb[i][1].y += on ? w1 * tanhf(v1.y + c1.y) : 0.f;
        }
    }
    __syncthreads();

    // ================= distant expert (CNF, 3 Euler steps) =================
    float2 x[RPT][2];
#pragma unroll
    for (int i = 0; i < RPT; i++) {
        int gr = base + r0 + i;
        float4 cv = make_float4(0.f, 0.f, 0.f, 0.f);
        if (gr < NCELLS) cv = *(const float4*)(cur + (size_t)gr * 64 + tx * 4);
        x[i][0] = make_float2(cv.x, cv.y);
        x[i][1] = make_float2(cv.z, cv.w);
    }
    const float DT = 1.0f / 3.0f;
    for (int step = 0; step < 3; step++) {
        // Xs = [x | mean_d]
#pragma unroll
        for (int i = 0; i < RPT; i++) {
            float4 xv = make_float4(x[i][0].x, x[i][0].y, x[i][1].x, x[i][1].y);
            *(float4*)&Xs[(r0 + i) * XP + tx * 4] = xv;
        }
        fillXright(Xs, g_mean_d, tid, base, nrows);
        loadW<128>(Wc1, Ws, tid);
        __syncthreads();
        ull av[RPT][4];
        gemm128<8>(Xs, Ws, r0, tx, av);
        __syncthreads();
        {
            float4 b0 = *(const float4*)&bc1[tx * 8];
            float4 b1 = *(const float4*)&bc1[tx * 8 + 4];
#pragma unroll
            for (int i = 0; i < RPT; i++) {
                float2 v0 = unpack2(av[i][0]), v1 = unpack2(av[i][1]);
                float2 v2 = unpack2(av[i][2]), v3 = unpack2(av[i][3]);
                float4 o0 = make_float4(tanhf(v0.x + b0.x), tanhf(v0.y + b0.y),
                                        tanhf(v1.x + b0.z), tanhf(v1.y + b0.w));
                float4 o1 = make_float4(tanhf(v2.x + b1.x), tanhf(v2.y + b1.y),
                                        tanhf(v3.x + b1.z), tanhf(v3.y + b1.w));
                *(float4*)&Xs[(r0 + i) * XP + tx * 8]     = o0;
                *(float4*)&Xs[(r0 + i) * XP + tx * 8 + 4] = o1;
            }
        }
        loadW<64>(Wc2, Ws, tid);
        __syncthreads();
        ull ad[RPT][2];
        gemm128<4>(Xs, Ws, r0, tx, ad);
        {
            float2 c0 = *(const float2*)&bc2[tx * 4];
            float2 c1 = *(const float2*)&bc2[tx * 4 + 2];
#pragma unroll
            for (int i = 0; i < RPT; i++) {
                float2 v0 = unpack2(ad[i][0]);
                float2 v1 = unpack2(ad[i][1]);
                x[i][0].x += DT * tanhf(v0.x + c0.x);
                x[i][0].y += DT * tanhf(v0.y + c0.y);
                x[i][1].x += DT * tanhf(v1.x + c1.x);
                x[i][1].y += DT * tanhf(v1.y + c1.y);
            }
        }
        __syncthreads();
    }
#pragma unroll
    for (int i = 0; i < RPT; i++) {
        int row = r0 + i;
        float w2 = sw[row * 4 + 2];
        bool on = (sflag[row] & 4);
        comb[i][0].x += on ? w2 * x[i][0].x : 0.f;
        comb[i][0].y += on ? w2 * x[i][0].y : 0.f;
        comb[i][1].x += on ? w2 * x[i][1].x : 0.f;
        comb[i][1].y += on ? w2 * x[i][1].y : 0.f;
    }

    // ================= store combined =================
#pragma unroll
    for (int i = 0; i < RPT; i++) {
        int gr = base + r0 + i;
        if (gr < NCELLS) {
            float4 o = make_float4(comb[i][0].x, comb[i][0].y,
                                   comb[i][1].x, comb[i][1].y);
            *(float4*)&out[(size_t)gr * 64 + tx * 4] = o;
        }
    }
}

// ---------------- launch ----------------
extern "C" void kernel_launch(void* const* d_in, const int* in_sizes, int n_in,
                              void* d_out, int out_size) {
    const float* cur = (const float*)d_in[0];
    const float* nb  = (const float*)d_in[1];
    const int*   cat = (const int*)d_in[2];
    const float* Wl  = (const float*)d_in[3];
    const float* bl  = (const float*)d_in[4];
    const float* Wf1 = (const float*)d_in[5];
    const float* bf1 = (const float*)d_in[6];
    const float* Wf2 = (const float*)d_in[7];
    const float* bf2 = (const float*)d_in[8];
    const float* Wc1 = (const float*)d_in[9];
    const float* bc1 = (const float*)d_in[10];
    const float* Wc2 = (const float*)d_in[11];
    const float* bc2 = (const float*)d_in[12];
    const float* Wg1 = (const float*)d_in[13];
    const float* bg1 = (const float*)d_in[14];
    const float* Wg2 = (const float*)d_in[15];
    const float* bg2 = (const float*)d_in[16];
    float* out = (float*)d_out;

    const int smem_bytes = (ROWS * XP + 128 * WPP + ROWS * 4 + ROWS) * 4;
    cudaFuncSetAttribute(moe_kernel, cudaFuncAttributeMaxDynamicSharedMemorySize,
                         smem_bytes);

    int agg_blocks = (NCELLS * 32 + 255) / 256;
    agg_kernel<<<agg_blocks, 256>>>(nb, cat);

    int moe_blocks = (NCELLS + ROWS - 1) / ROWS;   // 274 -> single wave at 2 CTA/SM
    moe_kernel<<<moe_blocks, NTHREADS, smem_bytes>>>(
        cur, Wl, bl, Wf1, bf1, Wf2, bf2, Wc1, bc1, Wc2, bc2,
        Wg1, bg1, Wg2, bg2, out, out_size);
}

// round 10
// speedup vs baseline: 1.7597x; 1.0207x over previous
#include <cuda_runtime.h>

#define NCELLS   19683
#define KNB      26
#define ROWS     72    // rows per CTA tile  -> grid 274 (single wave @ 2 CTA/SM)
#define NTHREADS 192   // 16 tx x 12 ty, 6 rows per thread
#define RPT      6     // rows per thread
#define XP       132   // Xs row pitch (floats)
#define WPP      132   // Ws row pitch (floats)
#define GSB      100   // Gs column base inside Ws rows (cols 100..131, unused by Wl)

// ---------------- scratch (device globals: allocation-free) ----------------
__device__ float g_mean_l[NCELLS * 64];
__device__ float g_mean_f[NCELLS * 64];
__device__ float g_mean_d[NCELLS * 64];
__device__ float g_act[NCELLS * 64];
__device__ int   g_flags[NCELLS];

typedef unsigned long long ull;

__device__ __forceinline__ ull pack2(float x, float y) {
    ull r; asm("mov.b64 %0, {%1,%2};" : "=l"(r) : "f"(x), "f"(y)); return r;
}
__device__ __forceinline__ float2 unpack2(ull v) {
    float2 r; asm("mov.b64 {%0,%1}, %2;" : "=f"(r.x), "=f"(r.y) : "l"(v)); return r;
}
__device__ __forceinline__ void ffma2(ull& acc, ull a, ull b) {
    asm("fma.rn.f32x2 %0, %1, %2, %0;" : "+l"(acc) : "l"(a), "l"(b));
}

// ---------------- cp.async helpers ----------------
__device__ __forceinline__ void cpa16(void* s, const void* g) {
    unsigned sa = (unsigned)__cvta_generic_to_shared(s);
    asm volatile("cp.async.ca.shared.global [%0], [%1], 16;" :: "r"(sa), "l"(g));
}
__device__ __forceinline__ void cpa16z(void* s, const void* g, int srcbytes) {
    unsigned sa = (unsigned)__cvta_generic_to_shared(s);
    asm volatile("cp.async.ca.shared.global [%0], [%1], 16, %2;"
                 :: "r"(sa), "l"(g), "r"(srcbytes));
}
__device__ __forceinline__ void cp_wait_all() {
    asm volatile("cp.async.wait_all;" ::: "memory");
}

// ---------------- kernel A: masked neighbor aggregation (branch-free) ------
__global__ void agg_kernel(const float* __restrict__ nb, const int* __restrict__ cat) {
    int gw = (blockIdx.x * blockDim.x + threadIdx.x) >> 5;
    if (gw >= NCELLS) return;
    int lane = threadIdx.x & 31;
    const float* base = nb + (size_t)gw * (KNB * 64);
    int myc = (lane < KNB) ? cat[gw * KNB + lane] : -1;

    unsigned m0 = __ballot_sync(0xffffffffu, myc == 0);
    unsigned m1 = __ballot_sync(0xffffffffu, myc == 1);
    unsigned m2 = __ballot_sync(0xffffffffu, myc == 2);

    float2 s0 = {0.f, 0.f}, s1 = {0.f, 0.f}, s2 = {0.f, 0.f}, sa = {0.f, 0.f};
#pragma unroll
    for (int k = 0; k < KNB; k++) {
        float2 v = *(const float2*)(base + k * 64 + lane * 2);
        sa.x += v.x; sa.y += v.y;
        bool b0 = (m0 >> k) & 1u;
        bool b1 = (m1 >> k) & 1u;
        bool b2 = (m2 >> k) & 1u;
        s0.x += b0 ? v.x : 0.f;  s0.y += b0 ? v.y : 0.f;
        s1.x += b1 ? v.x : 0.f;  s1.y += b1 ? v.y : 0.f;
        s2.x += b2 ? v.x : 0.f;  s2.y += b2 ? v.y : 0.f;
    }
    int c0 = __popc(m0), c1 = __popc(m1), c2 = __popc(m2);
    float d0 = fmaxf((float)c0, 1.0f);
    float d1 = fmaxf((float)c1, 1.0f);
    float d2 = fmaxf((float)c2, 1.0f);
    int off = gw * 64 + lane * 2;
    *(float2*)(g_mean_l + off) = make_float2(s0.x / d0, s0.y / d0);
    *(float2*)(g_mean_f + off) = make_float2(s1.x / d1, s1.y / d1);
    *(float2*)(g_mean_d + off) = make_float2(s2.x / d2, s2.y / d2);
    *(float2*)(g_act    + off) = make_float2(sa.x / 26.0f, sa.y / 26.0f);
    if (lane == 0)
        g_flags[gw] = (c0 > 0 ? 1 : 0) | (c1 > 0 ? 2 : 0) | (c2 > 0 ? 4 : 0);
}

// ---------------- kernel B helpers (async) ----------------
template <int NC>
__device__ __forceinline__ void loadW_async(const float* __restrict__ Wg, float* Ws, int tid) {
    constexpr int PR = NC / 4;  // float4 per row
    for (int i = tid; i < 128 * PR; i += NTHREADS) {
        int r = i / PR, c = i % PR;
        cpa16(&Ws[r * WPP + c * 4], Wg + 4 * i);
    }
}

// async fill Xs = [L | R]
__device__ __forceinline__ void fillX_async(float* Xs, const float* __restrict__ L,
                                            const float* __restrict__ R,
                                            int tid, int base, int nrows) {
#pragma unroll
    for (int i = tid; i < ROWS * 32; i += NTHREADS) {  // 12 iters exact
        int r = i >> 5;
        int c4 = i & 31;
        int gr = base + ((r < nrows) ? r : 0);
        const float* src = (c4 < 16) ? (L + (size_t)gr * 64 + (c4 << 2))
                                     : (R + (size_t)gr * 64 + ((c4 - 16) << 2));
        cpa16z(&Xs[r * XP + (c4 << 2)], src, (r < nrows) ? 16 : 0);
    }
}

// async fill only right half of Xs from R
__device__ __forceinline__ void fillXright_async(float* Xs, const float* __restrict__ R,
                                                 int tid, int base, int nrows) {
#pragma unroll
    for (int i = tid; i < ROWS * 16; i += NTHREADS) {  // 6 iters exact
        int r = i >> 4;
        int c4 = i & 15;
        int gr = base + ((r < nrows) ? r : 0);
        cpa16z(&Xs[r * XP + 64 + (c4 << 2)], R + (size_t)gr * 64 + (c4 << 2),
               (r < nrows) ? 16 : 0);
    }
}

// GEMM over K=128; fragment = RPT rows x TC cols per thread, packed f32x2 FMAs
template <int TC>
__device__ __forceinline__ void gemm128(const float* __restrict__ Xs,
                                        const float* __restrict__ Ws,
                                        int r0, int tx, ull (&acc)[RPT][TC / 2]) {
#pragma unroll
    for (int i = 0; i < RPT; i++)
#pragma unroll
        for (int j = 0; j < TC / 2; j++) acc[i][j] = 0ULL;

#pragma unroll 2
    for (int k = 0; k < 128; k += 4) {
        float4 a[RPT];
#pragma unroll
        for (int i = 0; i < RPT; i++) a[i] = *(const float4*)&Xs[(r0 + i) * XP + k];
#pragma unroll
        for (int kk = 0; kk < 4; kk++) {
            const float* bp = &Ws[(k + kk) * WPP + tx * TC];
            ull b[TC / 2];
            if constexpr (TC == 8) {
                ulonglong2 q0 = *(const ulonglong2*)bp;
                ulonglong2 q1 = *(const ulonglong2*)(bp + 4);
                b[0] = q0.x; b[1] = q0.y; b[2] = q1.x; b[3] = q1.y;
            } else if constexpr (TC == 4) {
                ulonglong2 q0 = *(const ulonglong2*)bp;
                b[0] = q0.x; b[1] = q0.y;
            } else {
                b[0] = *(const ull*)bp;
            }
#pragma unroll
            for (int i = 0; i < RPT; i++) {
                float av = ((const float*)&a[i])[kk];
                ull ap = pack2(av, av);
#pragma unroll
                for (int j = 0; j < TC / 2; j++) ffma2(acc[i][j], ap, b[j]);
            }
        }
    }
}

// ---------------- kernel B: fused MoE MLP stack (cp.async pipelined) -------
__global__ void __launch_bounds__(NTHREADS, 2)
moe_kernel(const float* __restrict__ cur,
           const float* __restrict__ Wl,  const float* __restrict__ bl,
           const float* __restrict__ Wf1, const float* __restrict__ bf1,
           const float* __restrict__ Wf2, const float* __restrict__ bf2,
           const float* __restrict__ Wc1, const float* __restrict__ bc1,
           const float* __restrict__ Wc2, const float* __restrict__ bc2,
           const float* __restrict__ Wg1, const float* __restrict__ bg1,
           const float* __restrict__ Wg2, const float* __restrict__ bg2,
           float* __restrict__ out, int out_size) {
    extern __shared__ float sm[];
    float* Xs    = sm;                       // [ROWS][XP]
    float* Ws    = Xs + ROWS * XP;           // [128][WPP]  (Gs in cols GSB..GSB+31)
    float* sw    = Ws + 128 * WPP;           // [ROWS][4]
    int*   sflag = (int*)(sw + ROWS * 4);    // [ROWS]

    int tid  = threadIdx.x;
    int base = blockIdx.x * ROWS;
    int nrows = min(ROWS, NCELLS - base);

    int tx = tid & 15;          // 0..15 (column group)
    int ty = tid >> 4;          // 0..11 (row group)
    int r0 = ty * RPT;

    // ================= prologue: gating inputs =================
    fillX_async(Xs, cur, g_act, tid, base, nrows);
    loadW_async<32>(Wg1, Ws, tid);
    if (tid < ROWS)
        sflag[tid] = (base + tid < NCELLS) ? g_flags[base + tid] : 0;
    cp_wait_all();
    __syncthreads();

    // ================= gating =================
    ull ag[RPT][1];
    gemm128<2>(Xs, Ws, r0, tx, ag);
    __syncthreads();           // all Xs/Ws reads done

    // prefetch local-expert data while writing Gs + reducing
    fillXright_async(Xs, g_mean_l, tid, base, nrows);   // Xs cols 64..127
    loadW_async<64>(Wl, Ws, tid);                       // Ws cols 0..63
    {
        float2 bg = *(const float2*)&bg1[tx * 2];
#pragma unroll
        for (int i = 0; i < RPT; i++) {
            int row = r0 + i;
            float2 v = unpack2(ag[i][0]);
            int k0 = tx * 2;
            Ws[row * WPP + GSB + ((k0 + row) & 31)]     = tanhf(v.x + bg.x);
            Ws[row * WPP + GSB + ((k0 + 1 + row) & 31)] = tanhf(v.y + bg.y);
        }
    }
    __syncthreads();
    if (tid < ROWS) {
        int row = tid;
        float l0 = bg2[0], l1 = bg2[1], l2 = bg2[2];
#pragma unroll
        for (int k = 0; k < 32; k++) {
            float gv = Ws[row * WPP + GSB + ((k + row) & 31)];
            l0 += gv * Wg2[k * 3 + 0];
            l1 += gv * Wg2[k * 3 + 1];
            l2 += gv * Wg2[k * 3 + 2];
        }
        float m = fmaxf(l0, fmaxf(l1, l2));
        float e0 = expf(l0 - m), e1 = expf(l1 - m), e2 = expf(l2 - m);
        float inv = 1.0f / (e0 + e1 + e2);
        float w0 = e0 * inv, w1 = e1 * inv, w2 = e2 * inv;
        sw[row * 4 + 0] = w0; sw[row * 4 + 1] = w1; sw[row * 4 + 2] = w2;
        int gr = base + row;
        if (gr < NCELLS && out_size >= NCELLS * 67) {
            out[(size_t)NCELLS * 64 + (size_t)gr * 3 + 0] = w0;
            out[(size_t)NCELLS * 64 + (size_t)gr * 3 + 1] = w1;
            out[(size_t)NCELLS * 64 + (size_t)gr * 3 + 2] = w2;
        }
    }
    cp_wait_all();
    __syncthreads();

    float2 comb[RPT][2];

    // ================= local expert =================
    {
        ull al[RPT][2];
        gemm128<4>(Xs, Ws, r0, tx, al);
        __syncthreads();       // Xs/Ws reads done
        // prefetch functional-expert data during epilogue
        fillXright_async(Xs, g_mean_f, tid, base, nrows);
        loadW_async<128>(Wf1, Ws, tid);
        float2 b0 = *(const float2*)&bl[tx * 4];
        float2 b1 = *(const float2*)&bl[tx * 4 + 2];
#pragma unroll
        for (int i = 0; i < RPT; i++) {
            int row = r0 + i;
            float w0 = sw[row * 4 + 0];
            bool on = (sflag[row] & 1);
            float2 v0 = unpack2(al[i][0]);
            float2 v1 = unpack2(al[i][1]);
            comb[i][0].x = on ? w0 * tanhf(v0.x + b0.x) : 0.f;
            comb[i][0].y = on ? w0 * tanhf(v0.y + b0.y) : 0.f;
            comb[i][1].x = on ? w0 * tanhf(v1.x + b1.x) : 0.f;
            comb[i][1].y = on ? w0 * tanhf(v1.y + b1.y) : 0.f;
        }
        cp_wait_all();
        __syncthreads();
    }

    // ================= functional expert =================
    {
        ull ah[RPT][4];
        gemm128<8>(Xs, Ws, r0, tx, ah);
        __syncthreads();       // all threads done reading Xs/Ws
        loadW_async<64>(Wf2, Ws, tid);   // overlaps tanh(h) epilogue
        float4 b0 = *(const float4*)&bf1[tx * 8];
        float4 b1 = *(const float4*)&bf1[tx * 8 + 4];
#pragma unroll
        for (int i = 0; i < RPT; i++) {
            float2 v0 = unpack2(ah[i][0]), v1 = unpack2(ah[i][1]);
            float2 v2 = unpack2(ah[i][2]), v3 = unpack2(ah[i][3]);
            float4 o0 = make_float4(tanhf(v0.x + b0.x), tanhf(v0.y + b0.y),
                                    tanhf(v1.x + b0.z), tanhf(v1.y + b0.w));
            float4 o1 = make_float4(tanhf(v2.x + b1.x), tanhf(v2.y + b1.y),
                                    tanhf(v3.x + b1.z), tanhf(v3.y + b1.w));
            *(float4*)&Xs[(r0 + i) * XP + tx * 8]     = o0;
            *(float4*)&Xs[(r0 + i) * XP + tx * 8 + 4] = o1;
        }
        cp_wait_all();
        __syncthreads();
    }
    float2 x[RPT][2];
    {
        ull af[RPT][2];
        gemm128<4>(Xs, Ws, r0, tx, af);
        __syncthreads();       // Xs/Ws reads done
        // prefetch CNF step-0 data during epilogue
        loadW_async<128>(Wc1, Ws, tid);
        fillXright_async(Xs, g_mean_d, tid, base, nrows);
        float2 c0 = *(const float2*)&bf2[tx * 4];
        float2 c1 = *(const float2*)&bf2[tx * 4 + 2];
#pragma unroll
        for (int i = 0; i < RPT; i++) {
            int row = r0 + i;
            float w1 = sw[row * 4 + 1];
            bool on = (sflag[row] & 2);
            float2 v0 = unpack2(af[i][0]);
            float2 v1 = unpack2(af[i][1]);
            comb[i][0].x += on ? w1 * tanhf(v0.x + c0.x) : 0.f;
            comb[i][0].y += on ? w1 * tanhf(v0.y + c0.y) : 0.f;
            comb[i][1].x += on ? w1 * tanhf(v1.x + c1.x) : 0.f;
            comb[i][1].y += on ? w1 * tanhf(v1.y + c1.y) : 0.f;
        }
        // CNF x init (plain LDG, overlaps copies) + stage x into Xs left half
#pragma unroll
        for (int i = 0; i < RPT; i++) {
            int gr = base + r0 + i;
            float4 cv = make_float4(0.f, 0.f, 0.f, 0.f);
            if (gr < NCELLS) cv = *(const float4*)(cur + (size_t)gr * 64 + tx * 4);
            x[i][0] = make_float2(cv.x, cv.y);
            x[i][1] = make_float2(cv.z, cv.w);
            *(float4*)&Xs[(r0 + i) * XP + tx * 4] = cv;
        }
        cp_wait_all();
        __syncthreads();
    }

    // ================= distant expert (CNF, 3 Euler steps) =================
    // loop invariant at top: Xs = [x | mean_d] valid, Ws = Wc1 valid, synced
    const float DT = 1.0f / 3.0f;
    for (int step = 0; step < 3; step++) {
        ull av[RPT][4];
        gemm128<8>(Xs, Ws, r0, tx, av);
        __syncthreads();
        loadW_async<64>(Wc2, Ws, tid);   // overlaps tanh(v) epilogue
        {
            float4 b0 = *(const float4*)&bc1[tx * 8];
            float4 b1 = *(const float4*)&bc1[tx * 8 + 4];
#pragma unroll
            for (int i = 0; i < RPT; i++) {
                float2 v0 = unpack2(av[i][0]), v1 = unpack2(av[i][1]);
                float2 v2 = unpack2(av[i][2]), v3 = unpack2(av[i][3]);
                float4 o0 = make_float4(tanhf(v0.x + b0.x), tanhf(v0.y + b0.y),
                                        tanhf(v1.x + b0.z), tanhf(v1.y + b0.w));
                float4 o1 = make_float4(tanhf(v2.x + b1.x), tanhf(v2.y + b1.y),
                                        tanhf(v3.x + b1.z), tanhf(v3.y + b1.w));
                *(float4*)&Xs[(r0 + i) * XP + tx * 8]     = o0;
                *(float4*)&Xs[(r0 + i) * XP + tx * 8 + 4] = o1;
            }
        }
        cp_wait_all();
        __syncthreads();
        ull ad[RPT][2];
        gemm128<4>(Xs, Ws, r0, tx, ad);
        __syncthreads();
        if (step < 2) {
            loadW_async<128>(Wc1, Ws, tid);            // next step's weights
            fillXright_async(Xs, g_mean_d, tid, base, nrows);  // restore mean_d
        }
        {
            float2 c0 = *(const float2*)&bc2[tx * 4];
            float2 c1 = *(const float2*)&bc2[tx * 4 + 2];
#pragma unroll
            for (int i = 0; i < RPT; i++) {
                float2 v0 = unpack2(ad[i][0]);
                float2 v1 = unpack2(ad[i][1]);
                x[i][0].x += DT * tanhf(v0.x + c0.x);
                x[i][0].y += DT * tanhf(v0.y + c0.y);
                x[i][1].x += DT * tanhf(v1.x + c1.x);
                x[i][1].y += DT * tanhf(v1.y + c1.y);
            }
        }
        if (step < 2) {
            // stage updated x into Xs left half for next step
#pragma unroll
            for (int i = 0; i < RPT; i++) {
                float4 xv = make_float4(x[i][0].x, x[i][0].y, x[i][1].x, x[i][1].y);
                *(float4*)&Xs[(r0 + i) * XP + tx * 4] = xv;
            }
            cp_wait_all();
            __syncthreads();
        }
    }
#pragma unroll
    for (int i = 0; i < RPT; i++) {
        int row = r0 + i;
        float w2 = sw[row * 4 + 2];
        bool on = (sflag[row] & 4);
        comb[i][0].x += on ? w2 * x[i][0].x : 0.f;
        comb[i][0].y += on ? w2 * x[i][0].y : 0.f;
        comb[i][1].x += on ? w2 * x[i][1].x : 0.f;
        comb[i][1].y += on ? w2 * x[i][1].y : 0.f;
    }

    // ================= store combined =================
#pragma unroll
    for (int i = 0; i < RPT; i++) {
        int gr = base + r0 + i;
        if (gr < NCELLS) {
            float4 o = make_float4(comb[i][0].x, comb[i][0].y,
                                   comb[i][1].x, comb[i][1].y);
            *(float4*)&out[(size_t)gr * 64 + tx * 4] = o;
        }
    }
}

// ---------------- launch ----------------
extern "C" void kernel_launch(void* const* d_in, const int* in_sizes, int n_in,
                              void* d_out, int out_size) {
    const float* cur = (const float*)d_in[0];
    const float* nb  = (const float*)d_in[1];
    const int*   cat = (const int*)d_in[2];
    const float* Wl  = (const float*)d_in[3];
    const float* bl  = (const float*)d_in[4];
    const float* Wf1 = (const float*)d_in[5];
    const float* bf1 = (const float*)d_in[6];
    const float* Wf2 = (const float*)d_in[7];
    const float* bf2 = (const float*)d_in[8];
    const float* Wc1 = (const float*)d_in[9];
    const float* bc1 = (const float*)d_in[10];
    const float* Wc2 = (const float*)d_in[11];
    const float* bc2 = (const float*)d_in[12];
    const float* Wg1 = (const float*)d_in[13];
    const float* bg1 = (const float*)d_in[14];
    const float* Wg2 = (const float*)d_in[15];
    const float* bg2 = (const float*)d_in[16];
    float* out = (float*)d_out;

    const int smem_bytes = (ROWS * XP + 128 * WPP + ROWS * 4 + ROWS) * 4;
    cudaFuncSetAttribute(moe_kernel, cudaFuncAttributeMaxDynamicSharedMemorySize,
                         smem_bytes);

    int agg_blocks = (NCELLS * 32 + 255) / 256;
    agg_kernel<<<agg_blocks, 256>>>(nb, cat);

    int moe_blocks = (NCELLS + ROWS - 1) / ROWS;   // 274 -> single wave at 2 CTA/SM
    moe_kernel<<<moe_blocks, NTHREADS, smem_bytes>>>(
        cur, Wl, bl, Wf1, bf1, Wf2, bf2, Wc1, bc1, Wc2, bc2,
        Wg1, bg1, Wg2, bg2, out, out_size);
}